// round 4
// baseline (speedup 1.0000x reference)
#include <cuda_runtime.h>
#include <math.h>

#define BATCH 256
#define N0 400
#define N1 200
#define N2 100
#define NT 50
#define NP 56      // col count for M / Y
#define LDA 51     // smem leading dim for Ts (odd -> conflict-free col walks)
#define LDB 52     // smem leading dim for Clenshaw buffers (float2-aligned)
#define NFEAT 1275
#define CHEB_D 8   // Chebyshev degree for matrix log

#define KC 40      // K-chunk in k_xm
#define XS_LD 80   // 8 row-groups * 10 (8 data + 2 pad) -> distinct banks per group
#define MS_LD 72   // 7 col-groups * 10 + 2

__device__ __align__(16) float g_T[N1 * NT];                 // W2@W3  (200x50)
__device__ __align__(16) float g_M[N0 * NP];                 // W1@W2@W3 padded (400x56)
__device__ __align__(16) float g_Y[(size_t)BATCH * N0 * NP]; // X@M    (256x400x56)
__device__ __align__(16) float g_Wsym[7 * NT * LDB];         // symmetrized head weights

// packed dual-fp32 FMA (ptxas never emits FFMA2 from C++; must come from PTX)
__device__ __forceinline__ void ffma2(float2& d, float2 a, float2 b) {
    asm("fma.rn.f32x2 %0, %1, %2, %0;"
        : "+l"(*reinterpret_cast<unsigned long long*>(&d))
        : "l"(*reinterpret_cast<unsigned long long*>(&a)),
          "l"(*reinterpret_cast<unsigned long long*>(&b)));
}

// ---------------- K1a: T = W2 @ W3 ----------------
__global__ void k_w2w3(const float* __restrict__ W2, const float* __restrict__ W3) {
    int stride = gridDim.x * blockDim.x;
    for (int t = blockIdx.x * blockDim.x + threadIdx.x; t < N1 * NT; t += stride) {
        int i = t / NT, j = t - (t / NT) * NT;
        float acc = 0.f;
        for (int k = 0; k < N2; k++) acc += W2[i * N2 + k] * W3[k * NT + j];
        g_T[t] = acc;
    }
}

// ---------------- K1b: M = W1 @ T (zero-padded to 56 cols) ----------------
__global__ void k_w1t(const float* __restrict__ W1) {
    int stride = gridDim.x * blockDim.x;
    for (int t = blockIdx.x * blockDim.x + threadIdx.x; t < N0 * NP; t += stride) {
        int i = t / NP, j = t - (t / NP) * NP;
        float acc = 0.f;
        if (j < NT) {
            for (int k = 0; k < N1; k++) acc += W1[i * N1 + k] * g_T[k * NT + j];
        }
        g_M[t] = acc;
    }
}

// ---------------- K1c: symmetrized head weights ----------------
// g_Wsym[c][i*52+j] so that  sum_{i,j} S[i,j]*Wsym[c][i,j] == feat @ Wl[c]
__global__ void k_wsym(const float* __restrict__ Wl) {
    int stride = gridDim.x * blockDim.x;
    for (int t = blockIdx.x * blockDim.x + threadIdx.x; t < 7 * NT * LDB; t += stride) {
        int c = t / (NT * LDB), l = t - c * (NT * LDB);
        int i = l / LDB, j = l - i * LDB;
        float v = 0.f;
        if (j < NT) {
            int lo = i < j ? i : j, hi = i < j ? j : i;
            int ti = lo * (101 - lo) / 2 + (hi - lo);
            float w = Wl[c * NFEAT + ti];
            v = (i == j) ? w : w * 0.70710678118654752f;  // sqrt(2)/2
        }
        g_Wsym[t] = v;
    }
}

// ---------------- K2: Y[b] = X[b] @ M  (400x400 @ 400x56) ----------------
// 64-thread blocks; tile 64 rows x 56 cols; microtile 8x8 (row-pair packed f32x2).
// A-tile loaded TRANSPOSED via X's symmetry (X row k == X col k) -> coalesced.
// Smem padded in groups of 8 (+2) so each group maps to distinct banks.
__global__ __launch_bounds__(64, 8) void k_xm(const float* __restrict__ X) {
    __shared__ float Xs[KC][XS_LD];   // [k][row-group-padded]
    __shared__ float Ms[KC][MS_LD];   // [k][col-group-padded]
    int b = blockIdx.y;
    int row0 = blockIdx.x * 64;
    int tid = threadIdx.x;
    int rg = tid / 7;   // 0..7 row group (8 rows)  [valid for tid<56]
    int cg = tid % 7;   // 0..6 col group (8 cols)
    const float* Xb = X + (size_t)b * N0 * N0;
    float* Yb = g_Y + (size_t)b * N0 * NP;
    float2 acc[4][8] = {};  // [row-pair][col]; .x=row 2rp, .y=row 2rp+1
    for (int kc = 0; kc < N0; kc += KC) {
        // stage Xs: 40x64 as float2 (1280 ops)
        for (int l = tid; l < KC * 32; l += 64) {
            int kk = l >> 5, p = l & 31;           // p: float2 idx in 64 cols
            int g = p >> 2, e = (p & 3) << 1;
            int col = row0 + (p << 1);
            float2 v = make_float2(0.f, 0.f);
            if (col < N0) v = *(const float2*)(Xb + (size_t)(kc + kk) * N0 + col);
            *(float2*)&Xs[kk][g * 10 + e] = v;
        }
        // stage Ms: 40x56 as float2 (1120 ops)
        for (int l = tid; l < KC * 28; l += 64) {
            int kk = l / 28, p = l - (l / 28) * 28;
            int g = p >> 2, e = (p & 3) << 1;
            float2 v = *(const float2*)(g_M + (kc + kk) * NP + (p << 1));
            *(float2*)&Ms[kk][g * 10 + e] = v;
        }
        __syncthreads();
        if (tid < 56) {
#pragma unroll 2
            for (int kk = 0; kk < KC; kk++) {
                float2 a0 = *(float2*)&Xs[kk][rg * 10 + 0];
                float2 a1 = *(float2*)&Xs[kk][rg * 10 + 2];
                float2 a2 = *(float2*)&Xs[kk][rg * 10 + 4];
                float2 a3 = *(float2*)&Xs[kk][rg * 10 + 6];
                float2 b0 = *(float2*)&Ms[kk][cg * 10 + 0];
                float2 b1 = *(float2*)&Ms[kk][cg * 10 + 2];
                float2 b2 = *(float2*)&Ms[kk][cg * 10 + 4];
                float2 b3 = *(float2*)&Ms[kk][cg * 10 + 6];
                float bd[8] = {b0.x, b0.y, b1.x, b1.y, b2.x, b2.y, b3.x, b3.y};
#pragma unroll
                for (int c = 0; c < 8; c++) {
                    float2 bc = make_float2(bd[c], bd[c]);
                    ffma2(acc[0][c], a0, bc);
                    ffma2(acc[1][c], a1, bc);
                    ffma2(acc[2][c], a2, bc);
                    ffma2(acc[3][c], a3, bc);
                }
            }
        }
        __syncthreads();
    }
    if (tid < 56) {
#pragma unroll
        for (int rp = 0; rp < 4; rp++) {
#pragma unroll
            for (int s = 0; s < 2; s++) {
                int row = row0 + rg * 8 + 2 * rp + s;
                if (row < N0) {
                    float4 v0, v1;
                    if (s == 0) {
                        v0 = make_float4(acc[rp][0].x, acc[rp][1].x, acc[rp][2].x, acc[rp][3].x);
                        v1 = make_float4(acc[rp][4].x, acc[rp][5].x, acc[rp][6].x, acc[rp][7].x);
                    } else {
                        v0 = make_float4(acc[rp][0].y, acc[rp][1].y, acc[rp][2].y, acc[rp][3].y);
                        v1 = make_float4(acc[rp][4].y, acc[rp][5].y, acc[rp][6].y, acc[rp][7].y);
                    }
                    *(float4*)(Yb + (size_t)row * NP + cg * 8) = v0;
                    *(float4*)(Yb + (size_t)row * NP + cg * 8 + 4) = v1;
                }
            }
        }
    }
}

// ---------------- K3: h = M^T Y, S = log(h) via Chebyshev/Clenshaw, head ----------------
// One batch per 256-thread block; matmuls on 250 threads (1 row x 10 cols, f32x2).
__global__ __launch_bounds__(256) void k_poly(const float* __restrict__ bl,
                                              float* __restrict__ out) {
    __shared__ float sTs[NT * LDA];     // h, then Ts
    __shared__ float sP0[NT * LDB];     // Clenshaw buf / staging M
    __shared__ float sP1[NT * LDB];     // Clenshaw buf / staging Y
    __shared__ float s_row[NT];
    __shared__ float s_bb;
    __shared__ float s_red[7 * 8];

    int b = blockIdx.x;
    int tid = threadIdx.x;
    const float* Yb = g_Y + (size_t)b * N0 * NP;

    int rg = tid / 5;          // 0..49 row       [valid tid<250]
    int cg = tid - rg * 5;     // 0..4  col group
    int j0 = cg * 10;

    // ---- h = M^T Y : 250 threads, 1x10 microtile, K staged in 50-row chunks ----
    float2 hv[5] = {};
    for (int kc = 0; kc < N0; kc += NT) {
        for (int l = tid; l < NT * NT; l += 256) {
            int r = l / NT, c = l - (l / NT) * NT;
            sP0[r * LDB + c] = g_M[(kc + r) * NP + c];
            sP1[r * LDB + c] = Yb[(kc + r) * NP + c];
        }
        __syncthreads();
        if (tid < 250) {
#pragma unroll 5
            for (int kk = 0; kk < NT; kk++) {
                float a = sP0[kk * LDB + rg];
                float2 ad = make_float2(a, a);
#pragma unroll
                for (int j = 0; j < 5; j++) {
                    float2 yv = *(float2*)&sP1[kk * LDB + j0 + 2 * j];
                    ffma2(hv[j], ad, yv);
                }
            }
        }
        __syncthreads();
    }
    if (tid < 250) {
#pragma unroll
        for (int j = 0; j < 5; j++) {
            sTs[rg * LDA + j0 + 2 * j] = hv[j].x;
            sTs[rg * LDA + j0 + 2 * j + 1] = hv[j].y;
        }
    }
    __syncthreads();

    // ---- Gershgorin upper bound (lower bound ~1 by construction) ----
    if (tid < NT) {
        float s = 0.f;
        for (int j = 0; j < NT; j++) s += fabsf(sTs[tid * LDA + j]);
        s_row[tid] = s;
    }
    __syncthreads();
    if (tid == 0) {
        float mx = 0.f;
        for (int i = 0; i < NT; i++) mx = fmaxf(mx, s_row[i]);
        s_bb = mx;
    }
    __syncthreads();
    float aa = 0.95f, bb = s_bb;
    float mid = 0.5f * (aa + bb);
    float kap = (bb - aa) / (bb + aa);
    float z = (1.f - sqrtf(fmaxf(1.f - kap * kap, 0.f))) / kap;
    float c0 = logf(mid) - logf(1.f + z * z);

    // ---- Ts = (2h - (a+b)I)/(b-a); zero Clenshaw buffers ----
    {
        float inv = 1.f / (bb - aa);
        for (int l = tid; l < NT * NT; l += 256) {
            int i = l / NT, j = l - (l / NT) * NT;
            sTs[i * LDA + j] = (2.f * sTs[i * LDA + j] - (i == j ? (aa + bb) : 0.f)) * inv;
        }
        for (int l = tid; l < NT * LDB; l += 256) {
            sP0[l] = 0.f;
            sP1[l] = 0.f;
        }
    }
    __syncthreads();

    // ---- Clenshaw: B_k = c_k I + 2 Ts B_{k+1} - B_{k+2} ----
    float* pb1 = sP0;
    float* pb2 = sP1;
    for (int k = CHEB_D; k >= 0; k--) {
        float ck, m2;
        if (k >= 1) {
            ck = 2.f * __powf(z, (float)k) / (float)k;
            if (!(k & 1)) ck = -ck;
            m2 = 2.f;
        } else {
            ck = c0;
            m2 = 1.f;
        }
        if (tid < 250) {
            float2 p[5] = {};
#pragma unroll 5
            for (int kk = 0; kk < NT; kk++) {
                float t = sTs[rg * LDA + kk];
                float2 td = make_float2(t, t);
#pragma unroll
                for (int j = 0; j < 5; j++) {
                    float2 bv = *(float2*)&pb1[kk * LDB + j0 + 2 * j];
                    ffma2(p[j], td, bv);
                }
            }
#pragma unroll
            for (int j = 0; j < 5; j++) {
                int jj = j0 + 2 * j;
                float2 o = *(float2*)&pb2[rg * LDB + jj];
                float2 n;
                n.x = m2 * p[j].x - o.x + (rg == jj ? ck : 0.f);
                n.y = m2 * p[j].y - o.y + (rg == jj + 1 ? ck : 0.f);
                *(float2*)&pb2[rg * LDB + jj] = n;
            }
        }
        __syncthreads();
        float* tmp = pb1; pb1 = pb2; pb2 = tmp;
    }
    float* S = pb1;  // result after final swap

    // ---- head: out[c] = <S, Wsym_c> + bl[c], full 50x52 dot (pads are zero) ----
    float po[7] = {0, 0, 0, 0, 0, 0, 0};
    for (int l = tid; l < NT * LDB; l += 256) {
        float s = S[l];
#pragma unroll
        for (int c = 0; c < 7; c++) po[c] += s * g_Wsym[c * (NT * LDB) + l];
    }
    int lane = tid & 31, warp = tid >> 5;
#pragma unroll
    for (int off = 16; off > 0; off >>= 1) {
#pragma unroll
        for (int c = 0; c < 7; c++) po[c] += __shfl_down_sync(0xffffffffu, po[c], off);
    }
    if (lane == 0) {
#pragma unroll
        for (int c = 0; c < 7; c++) s_red[c * 8 + warp] = po[c];
    }
    __syncthreads();
    if (tid < 7) {
        float sum = bl[tid];
#pragma unroll
        for (int w = 0; w < 8; w++) sum += s_red[tid * 8 + w];
        out[b * 7 + tid] = sum;
    }
}

extern "C" void kernel_launch(void* const* d_in, const int* in_sizes, int n_in,
                              void* d_out, int out_size) {
    const float* x  = (const float*)d_in[0];
    const float* W1 = (const float*)d_in[1];
    const float* W2 = (const float*)d_in[2];
    const float* W3 = (const float*)d_in[3];
    const float* Wl = (const float*)d_in[4];
    const float* bl = (const float*)d_in[5];
    float* out = (float*)d_out;

    k_w2w3<<<40, 256>>>(W2, W3);
    k_w1t<<<88, 256>>>(W1);
    k_wsym<<<72, 256>>>(Wl);
    k_xm<<<dim3(7, BATCH), 64>>>(x);
    k_poly<<<BATCH, 256>>>(bl, out);
}

// round 5
// speedup vs baseline: 1.0072x; 1.0072x over previous
#include <cuda_runtime.h>
#include <math.h>

#define BATCH 256
#define N0 400
#define N1 200
#define N2 100
#define NT 50
#define NP 56      // col count for M / Y
#define LDA 51     // smem leading dim for Ts (odd -> conflict-free col walks)
#define LDB 52     // smem leading dim for Clenshaw buffers (float2-aligned)
#define NFEAT 1275
#define CHEB_D 8   // Chebyshev degree for matrix log

#define KC 40      // K-chunk in k_xm
#define XS_LD 82   // 8 row-groups * 10 (8 data + 2 pad)
#define MD_LD 128  // 7 col-groups * 18 (16 dup data + 2 pad)

__device__ __align__(16) float g_T[N1 * NT];                 // W2@W3  (200x50)
__device__ __align__(16) float g_M[N0 * NP];                 // W1@W2@W3 padded (400x56)
__device__ __align__(16) float g_Y[(size_t)BATCH * N0 * NP]; // X@M    (256x400x56)
__device__ __align__(16) float g_Wsym[7 * NT * LDB];         // symmetrized head weights

// packed dual-fp32 FMA (ptxas never emits FFMA2 from C++; must come from PTX)
__device__ __forceinline__ void ffma2(float2& d, float2 a, float2 b) {
    asm("fma.rn.f32x2 %0, %1, %2, %0;"
        : "+l"(*reinterpret_cast<unsigned long long*>(&d))
        : "l"(*reinterpret_cast<unsigned long long*>(&a)),
          "l"(*reinterpret_cast<unsigned long long*>(&b)));
}

// ---------------- K1a: T = W2 @ W3 ----------------
__global__ void k_w2w3(const float* __restrict__ W2, const float* __restrict__ W3) {
    int stride = gridDim.x * blockDim.x;
    for (int t = blockIdx.x * blockDim.x + threadIdx.x; t < N1 * NT; t += stride) {
        int i = t / NT, j = t - (t / NT) * NT;
        float acc = 0.f;
        for (int k = 0; k < N2; k++) acc += W2[i * N2 + k] * W3[k * NT + j];
        g_T[t] = acc;
    }
}

// ---------------- K1b: M = W1 @ T (zero-padded to 56 cols) ----------------
__global__ void k_w1t(const float* __restrict__ W1) {
    int stride = gridDim.x * blockDim.x;
    for (int t = blockIdx.x * blockDim.x + threadIdx.x; t < N0 * NP; t += stride) {
        int i = t / NP, j = t - (t / NP) * NP;
        float acc = 0.f;
        if (j < NT) {
            for (int k = 0; k < N1; k++) acc += W1[i * N1 + k] * g_T[k * NT + j];
        }
        g_M[t] = acc;
    }
}

// ---------------- K1c: symmetrized head weights ----------------
__global__ void k_wsym(const float* __restrict__ Wl) {
    int stride = gridDim.x * blockDim.x;
    for (int t = blockIdx.x * blockDim.x + threadIdx.x; t < 7 * NT * LDB; t += stride) {
        int c = t / (NT * LDB), l = t - c * (NT * LDB);
        int i = l / LDB, j = l - i * LDB;
        float v = 0.f;
        if (j < NT) {
            int lo = i < j ? i : j, hi = i < j ? j : i;
            int ti = lo * (101 - lo) / 2 + (hi - lo);
            float w = Wl[c * NFEAT + ti];
            v = (i == j) ? w : w * 0.70710678118654752f;  // sqrt(2)/2
        }
        g_Wsym[t] = v;
    }
}

// ---------------- K2: Y[b] = X[b] @ M  (400x400 @ 400x56) ----------------
// 64-thread blocks; tile 64 rows x 56 cols; microtile 8x8 (row-pair packed f32x2).
// A-tile loaded TRANSPOSED via X's symmetry (X row k == X col k) -> coalesced.
// M staged as DUPLICATED pairs {v,v} so every broadcast B operand is a single
// conflict-free LDS.64 (no unpack MOVs in the inner loop).
__global__ __launch_bounds__(64, 8) void k_xm(const float* __restrict__ X) {
    __shared__ float Xs[KC][XS_LD];   // [k][row-group-padded]
    __shared__ float Md[KC][MD_LD];   // [k][col-group dup-padded]
    int b = blockIdx.y;
    int row0 = blockIdx.x * 64;
    int tid = threadIdx.x;
    int rg = tid / 7;   // 0..7 row group (8 rows)  [valid for tid<56]
    int cg = tid % 7;   // 0..6 col group (8 cols)
    const float* Xb = X + (size_t)b * N0 * N0;
    float* Yb = g_Y + (size_t)b * N0 * NP;
    float2 acc[4][8] = {};  // [row-pair][col]
    for (int kc = 0; kc < N0; kc += KC) {
        // stage Xs: 40x64 as float2
        for (int l = tid; l < KC * 32; l += 64) {
            int kk = l >> 5, p = l & 31;
            int g = p >> 2, e = (p & 3) << 1;
            int col = row0 + (p << 1);
            float2 v = make_float2(0.f, 0.f);
            if (col < N0) v = *(const float2*)(Xb + (size_t)(kc + kk) * N0 + col);
            *(float2*)&Xs[kk][g * 10 + e] = v;
        }
        // stage Md: 40x56 values, each duplicated into a {v,v} float2
        for (int l = tid; l < KC * 28; l += 64) {
            int kk = l / 28, p = l - (l / 28) * 28;   // p: source float2 idx
            float2 v = *(const float2*)(g_M + (kc + kk) * NP + (p << 1));
            int g = p >> 2, e = p & 3;
            *(float2*)&Md[kk][g * 18 + e * 4] = make_float2(v.x, v.x);
            *(float2*)&Md[kk][g * 18 + e * 4 + 2] = make_float2(v.y, v.y);
        }
        __syncthreads();
        if (tid < 56) {
#pragma unroll 4
            for (int kk = 0; kk < KC; kk++) {
                const float* xr = &Xs[kk][rg * 10];
                const float* mr = &Md[kk][cg * 18];
                float2 a0 = *(const float2*)&xr[0];
                float2 a1 = *(const float2*)&xr[2];
                float2 a2 = *(const float2*)&xr[4];
                float2 a3 = *(const float2*)&xr[6];
#pragma unroll
                for (int c = 0; c < 8; c++) {
                    float2 bc = *(const float2*)&mr[c * 2];
                    ffma2(acc[0][c], a0, bc);
                    ffma2(acc[1][c], a1, bc);
                    ffma2(acc[2][c], a2, bc);
                    ffma2(acc[3][c], a3, bc);
                }
            }
        }
        __syncthreads();
    }
    if (tid < 56) {
#pragma unroll
        for (int rp = 0; rp < 4; rp++) {
#pragma unroll
            for (int s = 0; s < 2; s++) {
                int row = row0 + rg * 8 + 2 * rp + s;
                if (row < N0) {
                    float4 v0, v1;
                    if (s == 0) {
                        v0 = make_float4(acc[rp][0].x, acc[rp][1].x, acc[rp][2].x, acc[rp][3].x);
                        v1 = make_float4(acc[rp][4].x, acc[rp][5].x, acc[rp][6].x, acc[rp][7].x);
                    } else {
                        v0 = make_float4(acc[rp][0].y, acc[rp][1].y, acc[rp][2].y, acc[rp][3].y);
                        v1 = make_float4(acc[rp][4].y, acc[rp][5].y, acc[rp][6].y, acc[rp][7].y);
                    }
                    *(float4*)(Yb + (size_t)row * NP + cg * 8) = v0;
                    *(float4*)(Yb + (size_t)row * NP + cg * 8 + 4) = v1;
                }
            }
        }
    }
}

// ---------------- K3: h = M^T Y, S = log(h) via Chebyshev/Clenshaw, head ----------------
// One batch per 256-thread block; matmuls on 125 threads (2 rows x 10 cols, f32x2).
__global__ __launch_bounds__(256) void k_poly(const float* __restrict__ bl,
                                              float* __restrict__ out) {
    __shared__ float sTs[NT * LDA];     // h, then Ts
    __shared__ float sP0[NT * LDB];     // Clenshaw buf / staging M
    __shared__ float sP1[NT * LDB];     // Clenshaw buf / staging Y
    __shared__ float s_row[NT];
    __shared__ float s_bb;
    __shared__ float s_red[7 * 8];

    int b = blockIdx.x;
    int tid = threadIdx.x;
    const float* Yb = g_Y + (size_t)b * N0 * NP;

    int rg = tid / 5;             // 0..24 (valid when tid<125)
    int cg = tid - rg * 5;        // 0..4
    int i0 = 2 * rg;
    int j0 = 10 * cg;

    // ---- h = M^T Y : 125 threads, 2x10 microtile, K staged in 50-row chunks ----
    float2 h0[5] = {}, h1[5] = {};
    for (int kc = 0; kc < N0; kc += NT) {
        for (int l = tid; l < NT * NT; l += 256) {
            int r = l / NT, c = l - (l / NT) * NT;
            sP0[r * LDB + c] = g_M[(kc + r) * NP + c];
            sP1[r * LDB + c] = Yb[(kc + r) * NP + c];
        }
        __syncthreads();
        if (tid < 125) {
#pragma unroll 5
            for (int kk = 0; kk < NT; kk++) {
                float m0 = sP0[kk * LDB + i0], m1 = sP0[kk * LDB + i0 + 1];
                float2 a0 = make_float2(m0, m0), a1 = make_float2(m1, m1);
#pragma unroll
                for (int j = 0; j < 5; j++) {
                    float2 yv = *(float2*)&sP1[kk * LDB + j0 + 2 * j];
                    ffma2(h0[j], a0, yv);
                    ffma2(h1[j], a1, yv);
                }
            }
        }
        __syncthreads();
    }
    if (tid < 125) {
#pragma unroll
        for (int j = 0; j < 5; j++) {
            sTs[i0 * LDA + j0 + 2 * j] = h0[j].x;
            sTs[i0 * LDA + j0 + 2 * j + 1] = h0[j].y;
            sTs[(i0 + 1) * LDA + j0 + 2 * j] = h1[j].x;
            sTs[(i0 + 1) * LDA + j0 + 2 * j + 1] = h1[j].y;
        }
    }
    __syncthreads();

    // ---- Gershgorin upper bound (lower bound ~1 by construction) ----
    if (tid < NT) {
        float s = 0.f;
        for (int j = 0; j < NT; j++) s += fabsf(sTs[tid * LDA + j]);
        s_row[tid] = s;
    }
    __syncthreads();
    if (tid == 0) {
        float mx = 0.f;
        for (int i = 0; i < NT; i++) mx = fmaxf(mx, s_row[i]);
        s_bb = mx;
    }
    __syncthreads();
    float aa = 0.95f, bb = s_bb;
    float mid = 0.5f * (aa + bb);
    float kap = (bb - aa) / (bb + aa);
    float z = (1.f - sqrtf(fmaxf(1.f - kap * kap, 0.f))) / kap;
    float c0 = logf(mid) - logf(1.f + z * z);

    // ---- Ts = (2h - (a+b)I)/(b-a); zero Clenshaw buffers ----
    {
        float inv = 1.f / (bb - aa);
        for (int l = tid; l < NT * NT; l += 256) {
            int i = l / NT, j = l - (l / NT) * NT;
            sTs[i * LDA + j] = (2.f * sTs[i * LDA + j] - (i == j ? (aa + bb) : 0.f)) * inv;
        }
        for (int l = tid; l < NT * LDB; l += 256) {
            sP0[l] = 0.f;
            sP1[l] = 0.f;
        }
    }
    __syncthreads();

    // ---- Clenshaw: B_k = c_k I + 2 Ts B_{k+1} - B_{k+2} ----
    float* pb1 = sP0;
    float* pb2 = sP1;
    for (int k = CHEB_D; k >= 0; k--) {
        float ck, m2;
        if (k >= 1) {
            ck = 2.f * __powf(z, (float)k) / (float)k;
            if (!(k & 1)) ck = -ck;
            m2 = 2.f;
        } else {
            ck = c0;
            m2 = 1.f;
        }
        if (tid < 125) {
            float2 p0[5] = {}, p1[5] = {};
#pragma unroll 5
            for (int kk = 0; kk < NT; kk++) {
                float t0 = sTs[i0 * LDA + kk], t1 = sTs[(i0 + 1) * LDA + kk];
                float2 td0 = make_float2(t0, t0), td1 = make_float2(t1, t1);
#pragma unroll
                for (int j = 0; j < 5; j++) {
                    float2 bv = *(float2*)&pb1[kk * LDB + j0 + 2 * j];
                    ffma2(p0[j], td0, bv);
                    ffma2(p1[j], td1, bv);
                }
            }
#pragma unroll
            for (int j = 0; j < 5; j++) {
                int jj = j0 + 2 * j;
                float2 o0 = *(float2*)&pb2[i0 * LDB + jj];
                float2 o1 = *(float2*)&pb2[(i0 + 1) * LDB + jj];
                float2 n0, n1;
                n0.x = m2 * p0[j].x - o0.x + (i0 == jj ? ck : 0.f);
                n0.y = m2 * p0[j].y - o0.y + (i0 == jj + 1 ? ck : 0.f);
                n1.x = m2 * p1[j].x - o1.x + (i0 + 1 == jj ? ck : 0.f);
                n1.y = m2 * p1[j].y - o1.y + (i0 + 1 == jj + 1 ? ck : 0.f);
                *(float2*)&pb2[i0 * LDB + jj] = n0;
                *(float2*)&pb2[(i0 + 1) * LDB + jj] = n1;
            }
        }
        __syncthreads();
        float* tmp = pb1; pb1 = pb2; pb2 = tmp;
    }
    float* S = pb1;  // result after final swap

    // ---- head: out[c] = <S, Wsym_c> + bl[c] (pads are zero on both sides) ----
    float po[7] = {0, 0, 0, 0, 0, 0, 0};
    for (int l = tid; l < NT * LDB; l += 256) {
        float s = S[l];
#pragma unroll
        for (int c = 0; c < 7; c++) po[c] += s * g_Wsym[c * (NT * LDB) + l];
    }
    int lane = tid & 31, warp = tid >> 5;
#pragma unroll
    for (int off = 16; off > 0; off >>= 1) {
#pragma unroll
        for (int c = 0; c < 7; c++) po[c] += __shfl_down_sync(0xffffffffu, po[c], off);
    }
    if (lane == 0) {
#pragma unroll
        for (int c = 0; c < 7; c++) s_red[c * 8 + warp] = po[c];
    }
    __syncthreads();
    if (tid < 7) {
        float sum = bl[tid];
#pragma unroll
        for (int w = 0; w < 8; w++) sum += s_red[tid * 8 + w];
        out[b * 7 + tid] = sum;
    }
}

extern "C" void kernel_launch(void* const* d_in, const int* in_sizes, int n_in,
                              void* d_out, int out_size) {
    const float* x  = (const float*)d_in[0];
    const float* W1 = (const float*)d_in[1];
    const float* W2 = (const float*)d_in[2];
    const float* W3 = (const float*)d_in[3];
    const float* Wl = (const float*)d_in[4];
    const float* bl = (const float*)d_in[5];
    float* out = (float*)d_out;

    k_w2w3<<<40, 256>>>(W2, W3);
    k_w1t<<<88, 256>>>(W1);
    k_wsym<<<72, 256>>>(Wl);
    k_xm<<<dim3(7, BATCH), 64>>>(x);
    k_poly<<<BATCH, 256>>>(bl, out);
}

// round 10
// speedup vs baseline: 1.2256x; 1.2168x over previous
#include <cuda_runtime.h>
#include <stdint.h>
#include <math.h>

#define BATCH 256
#define N0 400
#define N1 200
#define N2 100
#define NT 50
#define NP 56      // col count for M / Y
#define LDA 51     // smem leading dim for Ts (odd -> conflict-free col walks)
#define LDB 52     // smem leading dim for Clenshaw buffers (float2-aligned)
#define NFEAT 1275
#define CHEB_D 8   // Chebyshev degree for matrix log

#define KC 20        // K-chunk in k_xm
#define NCHUNK (N0 / KC)
#define XS_LD 96     // 8 row-groups * 12 (8 data + 4 pad) -> 16B aligned, distinct banks
#define MS_LD 84     // 7 col-groups * 12

__device__ __align__(16) float g_T[N1 * NT];                 // W2@W3  (200x50)
__device__ __align__(16) float g_M[N0 * NP];                 // W1@W2@W3 padded (400x56)
__device__ __align__(16) float g_Y[(size_t)BATCH * N0 * NP]; // X@M    (256x400x56)
__device__ __align__(16) float g_Wsym[7 * NT * LDB];         // symmetrized head weights

// packed dual-fp32 FMA (ptxas never emits FFMA2 from C++; must come from PTX)
__device__ __forceinline__ void ffma2(float2& d, float2 a, float2 b) {
    asm("fma.rn.f32x2 %0, %1, %2, %0;"
        : "+l"(*reinterpret_cast<unsigned long long*>(&d))
        : "l"(*reinterpret_cast<unsigned long long*>(&a)),
          "l"(*reinterpret_cast<unsigned long long*>(&b)));
}

__device__ __forceinline__ void cp16(unsigned int dst_smem, const void* src, int src_bytes) {
    asm volatile("cp.async.cg.shared.global [%0], [%1], 16, %2;"
                 :: "r"(dst_smem), "l"(src), "r"(src_bytes));
}
__device__ __forceinline__ void cp_commit() {
    asm volatile("cp.async.commit_group;");
}
template <int N>
__device__ __forceinline__ void cp_wait() {
    asm volatile("cp.async.wait_group %0;" :: "n"(N));
}

// ---------------- K1a: T = W2 @ W3 ----------------
__global__ void k_w2w3(const float* __restrict__ W2, const float* __restrict__ W3) {
    int stride = gridDim.x * blockDim.x;
    for (int t = blockIdx.x * blockDim.x + threadIdx.x; t < N1 * NT; t += stride) {
        int i = t / NT, j = t - (t / NT) * NT;
        float acc = 0.f;
        for (int k = 0; k < N2; k++) acc += W2[i * N2 + k] * W3[k * NT + j];
        g_T[t] = acc;
    }
}

// ---------------- K1b: M = W1 @ T (zero-padded to 56 cols) ----------------
__global__ void k_w1t(const float* __restrict__ W1) {
    int stride = gridDim.x * blockDim.x;
    for (int t = blockIdx.x * blockDim.x + threadIdx.x; t < N0 * NP; t += stride) {
        int i = t / NP, j = t - (t / NP) * NP;
        float acc = 0.f;
        if (j < NT) {
            for (int k = 0; k < N1; k++) acc += W1[i * N1 + k] * g_T[k * NT + j];
        }
        g_M[t] = acc;
    }
}

// ---------------- K1c: symmetrized head weights ----------------
__global__ void k_wsym(const float* __restrict__ Wl) {
    int stride = gridDim.x * blockDim.x;
    for (int t = blockIdx.x * blockDim.x + threadIdx.x; t < 7 * NT * LDB; t += stride) {
        int c = t / (NT * LDB), l = t - c * (NT * LDB);
        int i = l / LDB, j = l - i * LDB;
        float v = 0.f;
        if (j < NT) {
            int lo = i < j ? i : j, hi = i < j ? j : i;
            int ti = lo * (101 - lo) / 2 + (hi - lo);
            float w = Wl[c * NFEAT + ti];
            v = (i == j) ? w : w * 0.70710678118654752f;  // sqrt(2)/2
        }
        g_Wsym[t] = v;
    }
}

// ---------------- K2: Y[b] = X[b] @ M  (400x400 @ 400x56) ----------------
// 64-thread blocks; tile 64 rows x 56 cols; microtile 8x8 (row-pair packed f32x2).
// A-tile loaded TRANSPOSED via X's symmetry (X row k == X col k) -> coalesced.
// Double-buffered cp.async staging (KC=20); group-pad stride 12 -> all smem
// reads are conflict-free LDS.128.
__global__ __launch_bounds__(64) void k_xm(const float* __restrict__ X) {
    __shared__ __align__(16) float Xs[2][KC][XS_LD];
    __shared__ __align__(16) float Ms[2][KC][MS_LD];
    int b = blockIdx.y;
    int row0 = blockIdx.x * 64;
    int tid = threadIdx.x;
    int rg = tid / 7;   // 0..7 row group (8 rows)  [valid for tid<56]
    int cg = tid % 7;   // 0..6 col group (8 cols)
    const float* Xb = X + (size_t)b * N0 * N0;
    float* Yb = g_Y + (size_t)b * N0 * NP;

    unsigned int sXs = (unsigned int)__cvta_generic_to_shared(&Xs[0][0][0]);
    unsigned int sMs = (unsigned int)__cvta_generic_to_shared(&Ms[0][0][0]);

    // stage chunk c into buffer buf
    auto stage = [&](int c, int buf) {
        int kbase = c * KC;
        // Xs: KC x 64 floats as 16 float4/row
        for (int l = tid; l < KC * 16; l += 64) {
            int kk = l >> 4, p = l & 15;
            int g = p >> 1, e = p & 1;
            unsigned int dst =
                sXs + (unsigned int)((buf * KC * XS_LD + kk * XS_LD + g * 12 + e * 4) * 4);
            int col = row0 + p * 4;
            const float* src = Xb + (size_t)(kbase + kk) * N0 + col;
            cp16(dst, src, col <= N0 - 4 ? 16 : 0);
        }
        // Ms: KC x 56 floats as 14 float4/row
        for (int l = tid; l < KC * 14; l += 64) {
            int kk = l / 14, p = l - (l / 14) * 14;
            int g = p >> 1, e = p & 1;
            unsigned int dst =
                sMs + (unsigned int)((buf * KC * MS_LD + kk * MS_LD + g * 12 + e * 4) * 4);
            cp16(dst, g_M + (kbase + kk) * NP + p * 4, 16);
        }
        cp_commit();
    };

    float2 acc[4][8] = {};  // [row-pair][col]; .x=row 2rp, .y=row 2rp+1

    stage(0, 0);
    for (int c = 0; c < NCHUNK; c++) {
        int buf = c & 1;
        if (c + 1 < NCHUNK) {
            stage(c + 1, buf ^ 1);
            cp_wait<1>();
        } else {
            cp_wait<0>();
        }
        __syncthreads();
        if (tid < 56) {
#pragma unroll
            for (int kk = 0; kk < KC; kk++) {
                const float* xr = &Xs[buf][kk][rg * 12];
                const float* mr = &Ms[buf][kk][cg * 12];
                float4 av0 = *(const float4*)&xr[0];
                float4 av1 = *(const float4*)&xr[4];
                float4 bv0 = *(const float4*)&mr[0];
                float4 bv1 = *(const float4*)&mr[4];
                float2 a0 = make_float2(av0.x, av0.y);
                float2 a1 = make_float2(av0.z, av0.w);
                float2 a2 = make_float2(av1.x, av1.y);
                float2 a3 = make_float2(av1.z, av1.w);
                float bd[8] = {bv0.x, bv0.y, bv0.z, bv0.w, bv1.x, bv1.y, bv1.z, bv1.w};
#pragma unroll
                for (int cc = 0; cc < 8; cc++) {
                    float2 bc = make_float2(bd[cc], bd[cc]);
                    ffma2(acc[0][cc], a0, bc);
                    ffma2(acc[1][cc], a1, bc);
                    ffma2(acc[2][cc], a2, bc);
                    ffma2(acc[3][cc], a3, bc);
                }
            }
        }
        __syncthreads();
    }
    if (tid < 56) {
#pragma unroll
        for (int rp = 0; rp < 4; rp++) {
#pragma unroll
            for (int s = 0; s < 2; s++) {
                int row = row0 + rg * 8 + 2 * rp + s;
                if (row < N0) {
                    float4 v0, v1;
                    if (s == 0) {
                        v0 = make_float4(acc[rp][0].x, acc[rp][1].x, acc[rp][2].x, acc[rp][3].x);
                        v1 = make_float4(acc[rp][4].x, acc[rp][5].x, acc[rp][6].x, acc[rp][7].x);
                    } else {
                        v0 = make_float4(acc[rp][0].y, acc[rp][1].y, acc[rp][2].y, acc[rp][3].y);
                        v1 = make_float4(acc[rp][4].y, acc[rp][5].y, acc[rp][6].y, acc[rp][7].y);
                    }
                    *(float4*)(Yb + (size_t)row * NP + cg * 8) = v0;
                    *(float4*)(Yb + (size_t)row * NP + cg * 8 + 4) = v1;
                }
            }
        }
    }
}

// ---------------- K3: h = M^T Y, S = log(h) via Chebyshev/Clenshaw, head ----------------
// One batch per 256-thread block; matmuls on 125 threads (2 rows x 10 cols, f32x2).
__global__ __launch_bounds__(256) void k_poly(const float* __restrict__ bl,
                                              float* __restrict__ out) {
    __shared__ float sTs[NT * LDA];     // h, then Ts
    __shared__ float sP0[NT * LDB];     // Clenshaw buf / staging M
    __shared__ float sP1[NT * LDB];     // Clenshaw buf / staging Y
    __shared__ float s_row[NT];
    __shared__ float s_bb;
    __shared__ float s_red[7 * 8];

    int b = blockIdx.x;
    int tid = threadIdx.x;
    const float* Yb = g_Y + (size_t)b * N0 * NP;

    int rg = tid / 5;             // 0..24 (valid when tid<125)
    int cg = tid - rg * 5;        // 0..4
    int i0 = 2 * rg;
    int j0 = 10 * cg;

    // ---- h = M^T Y : 125 threads, 2x10 microtile, K staged in 50-row chunks ----
    float2 h0[5] = {}, h1[5] = {};
    for (int kc = 0; kc < N0; kc += NT) {
        for (int l = tid; l < NT * NT; l += 256) {
            int r = l / NT, c = l - (l / NT) * NT;
            sP0[r * LDB + c] = g_M[(kc + r) * NP + c];
            sP1[r * LDB + c] = Yb[(kc + r) * NP + c];
        }
        __syncthreads();
        if (tid < 125) {
#pragma unroll 5
            for (int kk = 0; kk < NT; kk++) {
                float m0 = sP0[kk * LDB + i0], m1 = sP0[kk * LDB + i0 + 1];
                float2 a0 = make_float2(m0, m0), a1 = make_float2(m1, m1);
#pragma unroll
                for (int j = 0; j < 5; j++) {
                    float2 yv = *(float2*)&sP1[kk * LDB + j0 + 2 * j];
                    ffma2(h0[j], a0, yv);
                    ffma2(h1[j], a1, yv);
                }
            }
        }
        __syncthreads();
    }
    if (tid < 125) {
#pragma unroll
        for (int j = 0; j < 5; j++) {
            sTs[i0 * LDA + j0 + 2 * j] = h0[j].x;
            sTs[i0 * LDA + j0 + 2 * j + 1] = h0[j].y;
            sTs[(i0 + 1) * LDA + j0 + 2 * j] = h1[j].x;
            sTs[(i0 + 1) * LDA + j0 + 2 * j + 1] = h1[j].y;
        }
    }
    __syncthreads();

    // ---- Gershgorin upper bound (lower bound ~1 by construction) ----
    if (tid < NT) {
        float s = 0.f;
        for (int j = 0; j < NT; j++) s += fabsf(sTs[tid * LDA + j]);
        s_row[tid] = s;
    }
    __syncthreads();
    if (tid == 0) {
        float mx = 0.f;
        for (int i = 0; i < NT; i++) mx = fmaxf(mx, s_row[i]);
        s_bb = mx;
    }
    __syncthreads();
    float aa = 0.95f, bb = s_bb;
    float mid = 0.5f * (aa + bb);
    float kap = (bb - aa) / (bb + aa);
    float z = (1.f - sqrtf(fmaxf(1.f - kap * kap, 0.f))) / kap;
    float c0 = logf(mid) - logf(1.f + z * z);

    // ---- Ts = (2h - (a+b)I)/(b-a); zero Clenshaw buffers ----
    {
        float inv = 1.f / (bb - aa);
        for (int l = tid; l < NT * NT; l += 256) {
            int i = l / NT, j = l - (l / NT) * NT;
            sTs[i * LDA + j] = (2.f * sTs[i * LDA + j] - (i == j ? (aa + bb) : 0.f)) * inv;
        }
        for (int l = tid; l < NT * LDB; l += 256) {
            sP0[l] = 0.f;
            sP1[l] = 0.f;
        }
    }
    __syncthreads();

    // ---- Clenshaw: B_k = c_k I + 2 Ts B_{k+1} - B_{k+2} ----
    float* pb1 = sP0;
    float* pb2 = sP1;
    for (int k = CHEB_D; k >= 0; k--) {
        float ck, m2;
        if (k >= 1) {
            ck = 2.f * __powf(z, (float)k) / (float)k;
            if (!(k & 1)) ck = -ck;
            m2 = 2.f;
        } else {
            ck = c0;
            m2 = 1.f;
        }
        if (tid < 125) {
            float2 p0[5] = {}, p1[5] = {};
#pragma unroll 5
            for (int kk = 0; kk < NT; kk++) {
                float t0 = sTs[i0 * LDA + kk], t1 = sTs[(i0 + 1) * LDA + kk];
                float2 td0 = make_float2(t0, t0), td1 = make_float2(t1, t1);
#pragma unroll
                for (int j = 0; j < 5; j++) {
                    float2 bv = *(float2*)&pb1[kk * LDB + j0 + 2 * j];
                    ffma2(p0[j], td0, bv);
                    ffma2(p1[j], td1, bv);
                }
            }
#pragma unroll
            for (int j = 0; j < 5; j++) {
                int jj = j0 + 2 * j;
                float2 o0 = *(float2*)&pb2[i0 * LDB + jj];
                float2 o1 = *(float2*)&pb2[(i0 + 1) * LDB + jj];
                float2 n0, n1;
                n0.x = m2 * p0[j].x - o0.x + (i0 == jj ? ck : 0.f);
                n0.y = m2 * p0[j].y - o0.y + (i0 == jj + 1 ? ck : 0.f);
                n1.x = m2 * p1[j].x - o1.x + (i0 + 1 == jj ? ck : 0.f);
                n1.y = m2 * p1[j].y - o1.y + (i0 + 1 == jj + 1 ? ck : 0.f);
                *(float2*)&pb2[i0 * LDB + jj] = n0;
                *(float2*)&pb2[(i0 + 1) * LDB + jj] = n1;
            }
        }
        __syncthreads();
        float* tmp = pb1; pb1 = pb2; pb2 = tmp;
    }
    float* S = pb1;  // result after final swap

    // ---- head: out[c] = <S, Wsym_c> + bl[c] (pads are zero on both sides) ----
    float po[7] = {0, 0, 0, 0, 0, 0, 0};
    for (int l = tid; l < NT * LDB; l += 256) {
        float s = S[l];
#pragma unroll
        for (int c = 0; c < 7; c++) po[c] += s * g_Wsym[c * (NT * LDB) + l];
    }
    int lane = tid & 31, warp = tid >> 5;
#pragma unroll
    for (int off = 16; off > 0; off >>= 1) {
#pragma unroll
        for (int c = 0; c < 7; c++) po[c] += __shfl_down_sync(0xffffffffu, po[c], off);
    }
    if (lane == 0) {
#pragma unroll
        for (int c = 0; c < 7; c++) s_red[c * 8 + warp] = po[c];
    }
    __syncthreads();
    if (tid < 7) {
        float sum = bl[tid];
#pragma unroll
        for (int w = 0; w < 8; w++) sum += s_red[tid * 8 + w];
        out[b * 7 + tid] = sum;
    }
}

extern "C" void kernel_launch(void* const* d_in, const int* in_sizes, int n_in,
                              void* d_out, int out_size) {
    const float* x  = (const float*)d_in[0];
    const float* W1 = (const float*)d_in[1];
    const float* W2 = (const float*)d_in[2];
    const float* W3 = (const float*)d_in[3];
    const float* Wl = (const float*)d_in[4];
    const float* bl = (const float*)d_in[5];
    float* out = (float*)d_out;

    k_w2w3<<<40, 256>>>(W2, W3);
    k_w1t<<<88, 256>>>(W1);
    k_wsym<<<72, 256>>>(Wl);
    k_xm<<<dim3(7, BATCH), 64>>>(x);
    k_poly<<<BATCH, 256>>>(bl, out);
}

// round 14
// speedup vs baseline: 1.6599x; 1.3544x over previous
#include <cuda_runtime.h>
#include <stdint.h>
#include <math.h>

#define BATCH 256
#define N0 400
#define N1 200
#define N2 100
#define NT 50
#define NP 56      // col count for M / Y
#define LDA 51     // smem leading dim for Ts (odd -> conflict-free col walks)
#define LDB 52     // smem leading dim for Clenshaw buffers (float2-aligned)
#define NFEAT 1275
#define CHEB_D 8   // Chebyshev degree for matrix log

#define NKCH 25    // K chunks of 16 in k_xmh

__device__ __align__(16) float g_T[N1 * NT];                 // W2@W3  (200x50)
__device__ __align__(16) float g_M[N0 * NP];                 // W1@W2@W3 padded (400x56)
__device__ __align__(16) float g_Y[(size_t)BATCH * N0 * NP]; // X@M    (256x400x56)
__device__ __align__(16) float g_Wsym[7 * NT * LDB];         // symmetrized head weights
// B = M as k-pair-packed bf16 (hi / lo split), [n][200 pairs]
__device__ __align__(16) unsigned g_Bph[56 * 200];
__device__ __align__(16) unsigned g_Bpl[56 * 200];

// packed dual-fp32 FMA
__device__ __forceinline__ void ffma2(float2& d, float2 a, float2 b) {
    asm("fma.rn.f32x2 %0, %1, %2, %0;"
        : "+l"(*reinterpret_cast<unsigned long long*>(&d))
        : "l"(*reinterpret_cast<unsigned long long*>(&a)),
          "l"(*reinterpret_cast<unsigned long long*>(&b)));
}

// pack two f32 to bf16x2: low half <- a, high half <- b
__device__ __forceinline__ unsigned pack_bf16x2(float a, float b) {
    unsigned r;
    asm("cvt.rn.bf16x2.f32 %0, %1, %2;" : "=r"(r) : "f"(b), "f"(a));
    return r;
}

__device__ __forceinline__ void cp16(unsigned dst_smem, const void* src, int src_bytes) {
    asm volatile("cp.async.cg.shared.global [%0], [%1], 16, %2;"
                 :: "r"(dst_smem), "l"(src), "r"(src_bytes));
}
__device__ __forceinline__ void cp_commit() {
    asm volatile("cp.async.commit_group;");
}
template <int N>
__device__ __forceinline__ void cp_wait() {
    asm volatile("cp.async.wait_group %0;" :: "n"(N));
}

// HMMA bf16: D(16x8,f32) += A(16x16) * B(16x8)
__device__ __forceinline__ void mma16816(float* d, const unsigned* a, unsigned b0,
                                         unsigned b1) {
    asm("mma.sync.aligned.m16n8k16.row.col.f32.bf16.bf16.f32 "
        "{%0,%1,%2,%3}, {%4,%5,%6,%7}, {%8,%9}, {%0,%1,%2,%3};"
        : "+f"(d[0]), "+f"(d[1]), "+f"(d[2]), "+f"(d[3])
        : "r"(a[0]), "r"(a[1]), "r"(a[2]), "r"(a[3]), "r"(b0), "r"(b1));
}

// ---------------- K1a: T = W2 @ W3 ----------------
__global__ void k_w2w3(const float* __restrict__ W2, const float* __restrict__ W3) {
    int stride = gridDim.x * blockDim.x;
    for (int t = blockIdx.x * blockDim.x + threadIdx.x; t < N1 * NT; t += stride) {
        int i = t / NT, j = t - (t / NT) * NT;
        float acc = 0.f;
        for (int k = 0; k < N2; k++) acc += W2[i * N2 + k] * W3[k * NT + j];
        g_T[t] = acc;
    }
}

// ---------------- K1b: M = W1 @ T (zero-padded to 56 cols) ----------------
__global__ void k_w1t(const float* __restrict__ W1) {
    int stride = gridDim.x * blockDim.x;
    for (int t = blockIdx.x * blockDim.x + threadIdx.x; t < N0 * NP; t += stride) {
        int i = t / NP, j = t - (t / NP) * NP;
        float acc = 0.f;
        if (j < NT) {
            for (int k = 0; k < N1; k++) acc += W1[i * N1 + k] * g_T[k * NT + j];
        }
        g_M[t] = acc;
    }
}

// ---------------- K1c: symmetrized head weights ----------------
__global__ void k_wsym(const float* __restrict__ Wl) {
    int stride = gridDim.x * blockDim.x;
    for (int t = blockIdx.x * blockDim.x + threadIdx.x; t < 7 * NT * LDB; t += stride) {
        int c = t / (NT * LDB), l = t - c * (NT * LDB);
        int i = l / LDB, j = l - i * LDB;
        float v = 0.f;
        if (j < NT) {
            int lo = i < j ? i : j, hi = i < j ? j : i;
            int ti = lo * (101 - lo) / 2 + (hi - lo);
            float w = Wl[c * NFEAT + ti];
            v = (i == j) ? w : w * 0.70710678118654752f;  // sqrt(2)/2
        }
        g_Wsym[t] = v;
    }
}

// ---------------- K1d: k-pair-packed bf16 split images of B = M ----------------
__global__ void k_bpk() {
    int t = blockIdx.x * blockDim.x + threadIdx.x;
    if (t >= 56 * 200) return;
    int n = t / 200, p = t - (t / 200) * 200;
    float m0 = g_M[(2 * p) * NP + n];
    float m1 = g_M[(2 * p + 1) * NP + n];
    unsigned h = pack_bf16x2(m0, m1);
    float f0 = __uint_as_float(h << 16);
    float f1 = __uint_as_float(h & 0xFFFF0000u);
    unsigned l = pack_bf16x2(m0 - f0, m1 - f1);
    g_Bph[n * 200 + p] = h;
    g_Bpl[n * 200 + p] = l;
}

// ---------------- K2: Y[b] = X[b] @ M via HMMA bf16 split ----------------
// grid (4, 256), 256 threads. Warp w: rows row0+16w..+15; 7 n-tiles of 8.
__global__ __launch_bounds__(256) void k_xmh(const float* __restrict__ X) {
    __shared__ __align__(16) unsigned sBh[2][672];  // [buf][n*12 + pair], pairs 0..7
    __shared__ __align__(16) unsigned sBl[2][672];
    int tid = threadIdx.x;
    int wid = tid >> 5, lane = tid & 31;
    int gid = lane >> 2, tig = lane & 3;
    int b = blockIdx.y;
    int r0 = blockIdx.x * 128 + wid * 16 + gid;
    int r1 = r0 + 8;
    const float* Xb = X + (size_t)b * N0 * N0;
    float* Yb = g_Y + (size_t)b * N0 * NP;

    unsigned sbh = (unsigned)__cvta_generic_to_shared(&sBh[0][0]);
    unsigned sbl = (unsigned)__cvta_generic_to_shared(&sBl[0][0]);

    float d[7][4];
#pragma unroll
    for (int t = 0; t < 7; t++)
#pragma unroll
        for (int e = 0; e < 4; e++) d[t][e] = 0.f;

    auto stageB = [&](int c, int buf) {
        if (tid < 224) {
            int n = tid >> 2, q = tid & 3;
            int e = q & 1;
            const unsigned* src = ((q >> 1) ? g_Bpl : g_Bph) + n * 200 + c * 8 + e * 4;
            unsigned base = (q >> 1) ? sbl : sbh;
            cp16(base + (unsigned)((buf * 672 + n * 12 + e * 4) * 4), src, 16);
        }
        cp_commit();
    };
    auto loadA = [&](float2* xa, int c) {
        int k0 = c * 16 + 2 * tig;
        float2 z = make_float2(0.f, 0.f);
        xa[0] = xa[1] = xa[2] = xa[3] = z;
        if (r0 < N0) {
            xa[0] = *(const float2*)(Xb + (size_t)r0 * N0 + k0);
            xa[2] = *(const float2*)(Xb + (size_t)r0 * N0 + k0 + 8);
        }
        if (r1 < N0) {
            xa[1] = *(const float2*)(Xb + (size_t)r1 * N0 + k0);
            xa[3] = *(const float2*)(Xb + (size_t)r1 * N0 + k0 + 8);
        }
    };

    float2 xn[4];
    stageB(0, 0);
    loadA(xn, 0);
    for (int c = 0; c < NKCH; c++) {
        int buf = c & 1;
        if (c + 1 < NKCH) {
            stageB(c + 1, buf ^ 1);
            cp_wait<1>();
        } else {
            cp_wait<0>();
        }
        __syncthreads();
        float2 xa[4];
#pragma unroll
        for (int e = 0; e < 4; e++) xa[e] = xn[e];
        if (c + 1 < NKCH) loadA(xn, c + 1);  // prefetch next chunk's A
        unsigned ah[4], al[4];
#pragma unroll
        for (int e = 0; e < 4; e++) {
            ah[e] = pack_bf16x2(xa[e].x, xa[e].y);
            float f0 = __uint_as_float(ah[e] << 16);
            float f1 = __uint_as_float(ah[e] & 0xFFFF0000u);
            al[e] = pack_bf16x2(xa[e].x - f0, xa[e].y - f1);
        }
#pragma unroll
        for (int t = 0; t < 7; t++) {
            int nb = (t * 8 + gid) * 12;
            unsigned bh0 = sBh[buf][nb + tig];
            unsigned bh1 = sBh[buf][nb + 4 + tig];
            unsigned bl0 = sBl[buf][nb + tig];
            unsigned bl1 = sBl[buf][nb + 4 + tig];
            mma16816(d[t], ah, bh0, bh1);   // hi*hi
            mma16816(d[t], al, bh0, bh1);   // lo*hi
            mma16816(d[t], ah, bl0, bl1);   // hi*lo
        }
        __syncthreads();
    }
#pragma unroll
    for (int t = 0; t < 7; t++) {
        int col = t * 8 + 2 * tig;
        if (r0 < N0) *(float2*)(Yb + (size_t)r0 * NP + col) = make_float2(d[t][0], d[t][1]);
        if (r1 < N0) *(float2*)(Yb + (size_t)r1 * NP + col) = make_float2(d[t][2], d[t][3]);
    }
}

// ---------------- K3: h = M^T Y, S = log(h) via Chebyshev/Clenshaw, head ----------------
// One batch per 256-thread block; matmuls on 125 threads (2 rows x 10 cols, f32x2).
__global__ __launch_bounds__(256) void k_poly(const float* __restrict__ bl,
                                              float* __restrict__ out) {
    __shared__ float sTs[NT * LDA];
    __shared__ float sP0[NT * LDB];
    __shared__ float sP1[NT * LDB];
    __shared__ float s_row[NT];
    __shared__ float s_bb;
    __shared__ float s_red[7 * 8];

    int b = blockIdx.x;
    int tid = threadIdx.x;
    const float* Yb = g_Y + (size_t)b * N0 * NP;

    int rg = tid / 5;
    int cg = tid - rg * 5;
    int i0 = 2 * rg;
    int j0 = 10 * cg;

    float2 h0[5] = {}, h1[5] = {};
    for (int kc = 0; kc < N0; kc += NT) {
        for (int l = tid; l < NT * NT; l += 256) {
            int r = l / NT, c = l - (l / NT) * NT;
            sP0[r * LDB + c] = g_M[(kc + r) * NP + c];
            sP1[r * LDB + c] = Yb[(kc + r) * NP + c];
        }
        __syncthreads();
        if (tid < 125) {
#pragma unroll 5
            for (int kk = 0; kk < NT; kk++) {
                float m0 = sP0[kk * LDB + i0], m1 = sP0[kk * LDB + i0 + 1];
                float2 a0 = make_float2(m0, m0), a1 = make_float2(m1, m1);
#pragma unroll
                for (int j = 0; j < 5; j++) {
                    float2 yv = *(float2*)&sP1[kk * LDB + j0 + 2 * j];
                    ffma2(h0[j], a0, yv);
                    ffma2(h1[j], a1, yv);
                }
            }
        }
        __syncthreads();
    }
    if (tid < 125) {
#pragma unroll
        for (int j = 0; j < 5; j++) {
            sTs[i0 * LDA + j0 + 2 * j] = h0[j].x;
            sTs[i0 * LDA + j0 + 2 * j + 1] = h0[j].y;
            sTs[(i0 + 1) * LDA + j0 + 2 * j] = h1[j].x;
            sTs[(i0 + 1) * LDA + j0 + 2 * j + 1] = h1[j].y;
        }
    }
    __syncthreads();

    if (tid < NT) {
        float s = 0.f;
        for (int j = 0; j < NT; j++) s += fabsf(sTs[tid * LDA + j]);
        s_row[tid] = s;
    }
    __syncthreads();
    if (tid == 0) {
        float mx = 0.f;
        for (int i = 0; i < NT; i++) mx = fmaxf(mx, s_row[i]);
        s_bb = mx;
    }
    __syncthreads();
    float aa = 0.95f, bb = s_bb;
    float mid = 0.5f * (aa + bb);
    float kap = (bb - aa) / (bb + aa);
    float z = (1.f - sqrtf(fmaxf(1.f - kap * kap, 0.f))) / kap;
    float c0 = logf(mid) - logf(1.f + z * z);

    {
        float inv = 1.f / (bb - aa);
        for (int l = tid; l < NT * NT; l += 256) {
            int i = l / NT, j = l - (l / NT) * NT;
            sTs[i * LDA + j] = (2.f * sTs[i * LDA + j] - (i == j ? (aa + bb) : 0.f)) * inv;
        }
        for (int l = tid; l < NT * LDB; l += 256) {
            sP0[l] = 0.f;
            sP1[l] = 0.f;
        }
    }
    __syncthreads();

    float* pb1 = sP0;
    float* pb2 = sP1;
    for (int k = CHEB_D; k >= 0; k--) {
        float ck, m2;
        if (k >= 1) {
            ck = 2.f * __powf(z, (float)k) / (float)k;
            if (!(k & 1)) ck = -ck;
            m2 = 2.f;
        } else {
            ck = c0;
            m2 = 1.f;
        }
        if (tid < 125) {
            float2 p0[5] = {}, p1[5] = {};
#pragma unroll 5
            for (int kk = 0; kk < NT; kk++) {
                float t0 = sTs[i0 * LDA + kk], t1 = sTs[(i0 + 1) * LDA + kk];
                float2 td0 = make_float2(t0, t0), td1 = make_float2(t1, t1);
#pragma unroll
                for (int j = 0; j < 5; j++) {
                    float2 bv = *(float2*)&pb1[kk * LDB + j0 + 2 * j];
                    ffma2(p0[j], td0, bv);
                    ffma2(p1[j], td1, bv);
                }
            }
#pragma unroll
            for (int j = 0; j < 5; j++) {
                int jj = j0 + 2 * j;
                float2 o0 = *(float2*)&pb2[i0 * LDB + jj];
                float2 o1 = *(float2*)&pb2[(i0 + 1) * LDB + jj];
                float2 n0, n1;
                n0.x = m2 * p0[j].x - o0.x + (i0 == jj ? ck : 0.f);
                n0.y = m2 * p0[j].y - o0.y + (i0 == jj + 1 ? ck : 0.f);
                n1.x = m2 * p1[j].x - o1.x + (i0 + 1 == jj ? ck : 0.f);
                n1.y = m2 * p1[j].y - o1.y + (i0 + 1 == jj + 1 ? ck : 0.f);
                *(float2*)&pb2[i0 * LDB + jj] = n0;
                *(float2*)&pb2[(i0 + 1) * LDB + jj] = n1;
            }
        }
        __syncthreads();
        float* tmp = pb1; pb1 = pb2; pb2 = tmp;
    }
    float* S = pb1;

    float po[7] = {0, 0, 0, 0, 0, 0, 0};
    for (int l = tid; l < NT * LDB; l += 256) {
        float s = S[l];
#pragma unroll
        for (int c = 0; c < 7; c++) po[c] += s * g_Wsym[c * (NT * LDB) + l];
    }
    int lane = tid & 31, warp = tid >> 5;
#pragma unroll
    for (int off = 16; off > 0; off >>= 1) {
#pragma unroll
        for (int c = 0; c < 7; c++) po[c] += __shfl_down_sync(0xffffffffu, po[c], off);
    }
    if (lane == 0) {
#pragma unroll
        for (int c = 0; c < 7; c++) s_red[c * 8 + warp] = po[c];
    }
    __syncthreads();
    if (tid < 7) {
        float sum = bl[tid];
#pragma unroll
        for (int w = 0; w < 8; w++) sum += s_red[tid * 8 + w];
        out[b * 7 + tid] = sum;
    }
}

extern "C" void kernel_launch(void* const* d_in, const int* in_sizes, int n_in,
                              void* d_out, int out_size) {
    const float* x  = (const float*)d_in[0];
    const float* W1 = (const float*)d_in[1];
    const float* W2 = (const float*)d_in[2];
    const float* W3 = (const float*)d_in[3];
    const float* Wl = (const float*)d_in[4];
    const float* bl = (const float*)d_in[5];
    float* out = (float*)d_out;

    k_w2w3<<<40, 256>>>(W2, W3);
    k_w1t<<<88, 256>>>(W1);
    k_bpk<<<44, 256>>>();
    k_wsym<<<72, 256>>>(Wl);
    k_xmh<<<dim3(4, BATCH), 256>>>(x);
    k_poly<<<BATCH, 256>>>(bl, out);
}